// round 8
// baseline (speedup 1.0000x reference)
#include <cuda_runtime.h>
#include <cuda_fp16.h>
#include <cstdint>

#define CB    2
#define CHW   4096
#define CHID  1280
#define CCAD  2048
#define CLTXT 77
#define CNT   4
#define CNH   20
#define CENCL (CLTXT + CNT)
#define NSPLIT 8
#define KSLICE (CCAD / NSPLIT)   // 256

#define GM 8192
#define GK 1280
#define GN 1280
#define CBSZ (CB * 80 * CHID)

// ---------------- scratch (device globals) ----------------
__device__ float g_q[(size_t)GM * GK];
__device__ float g_proj[(size_t)4 * NSPLIT * CBSZ];
__device__ float g_kv[(size_t)4 * CBSZ];
__device__ __half g_hid[(size_t)GM * GK];
__device__ __half g_wq[(size_t)GK * GN];
__device__ __half g_wo[(size_t)GK * GN];
__device__ __half g_attn[(size_t)GM * GK];

// =====================================================================
// fp32 -> fp16 convert
// =====================================================================
__global__ __launch_bounds__(512) void cvtf(
    const float* __restrict__ x, __half* __restrict__ y, int n)
{
    for (int i = (blockIdx.x * 512 + threadIdx.x) * 4; i < n; i += gridDim.x * 512 * 4) {
        const float4 v = *(const float4*)(x + i);
        *(__half2*)(y + i)     = __floats2half2_rn(v.x, v.y);
        *(__half2*)(y + i + 2) = __floats2half2_rn(v.z, v.w);
    }
}

// =====================================================================
// fp16 mma.sync GEMM: C[GM,GN] = A@B (+bias), fp32 accum
// CTA 128x128, 512 thr (16 warps 4x4), warp tile 32x32, BK=32
// 4-stage cp.async ring, one __syncthreads per k-tile.
// =====================================================================
#define CP_ASYNC(dst, src) asm volatile("cp.async.cg.shared.global [%0], [%1], 16;" :: "r"(dst), "l"(src))

__device__ __forceinline__ void ldsm4(uint32_t* r, uint32_t a) {
    asm volatile("ldmatrix.sync.aligned.m8n8.x4.shared.b16 {%0,%1,%2,%3}, [%4];"
        : "=r"(r[0]), "=r"(r[1]), "=r"(r[2]), "=r"(r[3]) : "r"(a));
}
__device__ __forceinline__ void ldsm4t(uint32_t* r, uint32_t a) {
    asm volatile("ldmatrix.sync.aligned.m8n8.x4.trans.shared.b16 {%0,%1,%2,%3}, [%4];"
        : "=r"(r[0]), "=r"(r[1]), "=r"(r[2]), "=r"(r[3]) : "r"(a));
}
__device__ __forceinline__ void mma16816(float* c, const uint32_t* a, const uint32_t* b) {
    asm volatile("mma.sync.aligned.m16n8k16.row.col.f32.f16.f16.f32 "
        "{%0,%1,%2,%3}, {%4,%5,%6,%7}, {%8,%9}, {%0,%1,%2,%3};"
        : "+f"(c[0]), "+f"(c[1]), "+f"(c[2]), "+f"(c[3])
        : "r"(a[0]), "r"(a[1]), "r"(a[2]), "r"(a[3]), "r"(b[0]), "r"(b[1]));
}

#define A_PITCH 40
#define B_PITCH 136
#define ABUF (128 * A_PITCH)
#define BBUF (32 * B_PITCH)
#define NSTAGE 4
#define GEMM_SMEM ((NSTAGE * ABUF + NSTAGE * BBUF) * 2)

__global__ __launch_bounds__(512, 1) void gemm_f16(
    const __half* __restrict__ A, const __half* __restrict__ B,
    const float* __restrict__ bias, float* __restrict__ C)
{
    extern __shared__ __align__(16) char sm[];
    __half* sA = (__half*)sm;              // [NSTAGE][ABUF]
    __half* sB = sA + NSTAGE * ABUF;       // [NSTAGE][BBUF]

    const int tid = threadIdx.x;
    const int m0 = blockIdx.x * 128, n0 = blockIdx.y * 128;
    const int lane = tid & 31, warp = tid >> 5;
    const int wm = warp >> 2, wn = warp & 3;

    const int arow = tid >> 2, ak8 = (tid & 3) << 3;
    const int brow = tid >> 4, bn8 = (tid & 15) << 3;
    const __half* gA = A + (size_t)(m0 + arow) * GK + ak8;
    const __half* gB = B + (size_t)brow * GN + n0 + bn8;
    const uint32_t dA = (uint32_t)__cvta_generic_to_shared(sA) + (uint32_t)(arow * A_PITCH + ak8) * 2;
    const uint32_t dB = (uint32_t)__cvta_generic_to_shared(sB) + (uint32_t)(brow * B_PITCH + bn8) * 2;

#define LOADK(stage, kt) do {                                                   \
        const uint32_t ao_ = (uint32_t)(stage) * (ABUF * 2);                    \
        const uint32_t bo_ = (uint32_t)(stage) * (BBUF * 2);                    \
        const size_t kofs_ = (size_t)(kt) * 32;                                 \
        CP_ASYNC(dA + ao_, gA + kofs_);                                         \
        CP_ASYNC(dB + bo_, gB + kofs_ * GN);                                    \
        asm volatile("cp.async.commit_group;");                                 \
    } while (0)

    LOADK(0, 0);
    LOADK(1, 1);
    LOADK(2, 2);

    float acc[2][4][4] = {};

    const uint32_t aOff = (uint32_t)((wm * 32 + (lane & 15)) * A_PITCH + ((lane >> 4) << 3)) * 2;
    const uint32_t aB0 = (uint32_t)__cvta_generic_to_shared(sA) + aOff;
    const uint32_t bOff = (uint32_t)(((lane & 7) + ((lane >> 3) & 1) * 8) * B_PITCH
                                     + wn * 32 + ((lane >> 4) << 3)) * 2;
    const uint32_t bB0 = (uint32_t)__cvta_generic_to_shared(sB) + bOff;

    const int NKT = GK / 32;   // 40
    for (int kt = 0; kt < NKT; kt++) {
        const int s = kt & (NSTAGE - 1);
        if (kt < NKT - 2)       asm volatile("cp.async.wait_group 2;");
        else if (kt == NKT - 2) asm volatile("cp.async.wait_group 1;");
        else                    asm volatile("cp.async.wait_group 0;");
        __syncthreads();

        const uint32_t ah = aB0 + s * (ABUF * 2);
        const uint32_t bh = bB0 + s * (BBUF * 2);
#pragma unroll
        for (int ks = 0; ks < 2; ks++) {
            const uint32_t ka = ah + ks * 32;
            const uint32_t kb = bh + ks * (16 * B_PITCH * 2);
            uint32_t A0[4], A1[4];
            ldsm4(A0, ka);
            ldsm4(A1, ka + 16 * A_PITCH * 2);
            uint32_t Bf[8];
            ldsm4t(Bf,     kb);
            ldsm4t(Bf + 4, kb + 32);
#pragma unroll
            for (int j = 0; j < 4; j++) {
                mma16816(acc[0][j], A0, &Bf[j * 2]);
                mma16816(acc[1][j], A1, &Bf[j * 2]);
            }
        }
        if (kt + 3 < NKT) {
            LOADK((kt + 3) & (NSTAGE - 1), kt + 3);
        }
    }

#pragma unroll
    for (int fm = 0; fm < 2; fm++) {
        const int r0 = m0 + wm * 32 + fm * 16 + (lane >> 2);
#pragma unroll
        for (int j = 0; j < 4; j++) {
            const int cc = n0 + wn * 32 + j * 8 + ((lane & 3) << 1);
            float b0 = 0.f, b1 = 0.f;
            if (bias) { b0 = bias[cc]; b1 = bias[cc + 1]; }
            *(float2*)(C + (size_t)r0 * GN + cc) =
                make_float2(acc[fm][j][0] + b0, acc[fm][j][1] + b1);
            *(float2*)(C + (size_t)(r0 + 8) * GN + cc) =
                make_float2(acc[fm][j][2] + b0, acc[fm][j][3] + b1);
        }
    }
}

// =====================================================================
// Projections (K/V/KN/VN), split-K fp32, 8 splits
// =====================================================================
__global__ __launch_bounds__(256) void proj_splitk(
    const float* __restrict__ enc,
    const float* __restrict__ Wk,  const float* __restrict__ Wv,
    const float* __restrict__ Wkn, const float* __restrict__ Wvn)
{
    __shared__ float As[16][68];
    __shared__ float Ws[16][64];
    const int type = blockIdx.z >> 3, split = blockIdx.z & 7;
    const int b = blockIdx.x >> 1, rowtile = blockIdx.x & 1;
    const int M = (type < 2) ? CLTXT : CNT;
    if (rowtile && M <= 64) return;
    const int col0 = blockIdx.y * 64;
    const int row0 = rowtile * 64;
    const float* W = (type == 0) ? Wk : (type == 1) ? Wv : (type == 2) ? Wkn : Wvn;
    const float* A = enc + (size_t)b * CENCL * CCAD + ((type >= 2) ? (size_t)CLTXT * CCAD : 0);
    float* C = g_proj + ((size_t)blockIdx.z * CB + b) * 80 * CHID;

    const int tid = threadIdx.x, tx = tid & 15, ty = tid >> 4;
    const int ar = tid >> 2, ak = (tid & 3) << 2;
    const int wk = tid >> 4, wc = (tid & 15) << 2;
    const bool aok = (row0 + ar) < M;
    const float* Aptr = A + (size_t)(row0 + ar) * CCAD + split * KSLICE + ak;
    const float* Wptr = W + (size_t)(split * KSLICE + wk) * CHID + col0 + wc;

    float acc[4][4] = {};
    for (int k0 = 0; k0 < KSLICE; k0 += 16) {
        float4 av = make_float4(0.f, 0.f, 0.f, 0.f);
        if (aok) av = *(const float4*)(Aptr + k0);
        As[ak + 0][ar] = av.x; As[ak + 1][ar] = av.y;
        As[ak + 2][ar] = av.z; As[ak + 3][ar] = av.w;
        *(float4*)&Ws[wk][wc] = *(const float4*)(Wptr + (size_t)k0 * CHID);
        __syncthreads();
#pragma unroll
        for (int kk = 0; kk < 16; kk++) {
            const float4 a4 = *(const float4*)&As[kk][ty * 4];
            const float4 b4 = *(const float4*)&Ws[kk][tx * 4];
            acc[0][0] += a4.x * b4.x; acc[0][1] += a4.x * b4.y; acc[0][2] += a4.x * b4.z; acc[0][3] += a4.x * b4.w;
            acc[1][0] += a4.y * b4.x; acc[1][1] += a4.y * b4.y; acc[1][2] += a4.y * b4.z; acc[1][3] += a4.y * b4.w;
            acc[2][0] += a4.z * b4.x; acc[2][1] += a4.z * b4.y; acc[2][2] += a4.z * b4.z; acc[2][3] += a4.z * b4.w;
            acc[3][0] += a4.w * b4.x; acc[3][1] += a4.w * b4.y; acc[3][2] += a4.w * b4.z; acc[3][3] += a4.w * b4.w;
        }
        __syncthreads();
    }
#pragma unroll
    for (int i = 0; i < 4; i++) {
        const int r = row0 + ty * 4 + i;
        if (r < M)
            *(float4*)(C + (size_t)r * CHID + col0 + tx * 4) =
                make_float4(acc[i][0], acc[i][1], acc[i][2], acc[i][3]);
    }
}

// =====================================================================
// reduce split-K partials once
// =====================================================================
__global__ __launch_bounds__(512) void reduce_proj()
{
    const int f = blockIdx.x * 512 + threadIdx.x;
    if (f >= 4 * CBSZ / 4) return;
    const int e = f * 4;
    const int t = e / CBSZ;
    const int inner = e - t * CBSZ;
    float4 s = make_float4(0.f, 0.f, 0.f, 0.f);
#pragma unroll
    for (int sp = 0; sp < NSPLIT; sp++) {
        const float4 v = *(const float4*)(g_proj + (size_t)(t * NSPLIT + sp) * CBSZ + inner);
        s.x += v.x; s.y += v.y; s.z += v.z; s.w += v.w;
    }
    *(float4*)(g_kv + (size_t)t * CBSZ + inner) = s;
}

// =====================================================================
// Attention: token-batched phase 3; output written as fp16
// =====================================================================
struct SmA {
    float Qs[2][64][68];
    float Ks[2][CLTXT][68];
    float Vs[2][CLTXT][68];
    float KNs[2][CNT][68];
    float VNs[2][CNT][68];
    float Wbuf[8][8][80];
};

__global__ __launch_bounds__(256, 1) void qattn_lite(const int* __restrict__ idx_alter)
{
    extern __shared__ char raw[];
    SmA& S = *reinterpret_cast<SmA*>(raw);
    const int b  = blockIdx.x >> 6;
    const int t0 = (blockIdx.x & 63) << 6;
    const int h0 = blockIdx.y * 2;
    const int tid = threadIdx.x;

    for (int i = tid; i < 64 * 32; i += 256) {
        const int t = i >> 5, c4 = (i & 31) << 2;
        const int hh = c4 >> 6, d = c4 & 63;
        float4 q = *(const float4*)(g_q + ((size_t)b * CHW + t0 + t) * CHID + h0 * 64 + c4);
        q.x *= 0.125f; q.y *= 0.125f; q.z *= 0.125f; q.w *= 0.125f;
        *(float4*)&S.Qs[hh][t][d] = q;
    }

#pragma unroll
    for (int hh = 0; hh < 2; hh++) {
        const size_t cb = (size_t)(h0 + hh) * 64;
        const float* kK = g_kv + (size_t)0 * CBSZ + (size_t)b * 80 * CHID + cb;
        const float* kV = g_kv + (size_t)1 * CBSZ + (size_t)b * 80 * CHID + cb;
        for (int i = tid; i < CLTXT * 16; i += 256) {
            const int j = i >> 4, d4 = (i & 15) << 2;
            *(float4*)&S.Ks[hh][j][d4] = *(const float4*)(kK + (size_t)j * CHID + d4);
            *(float4*)&S.Vs[hh][j][d4] = *(const float4*)(kV + (size_t)j * CHID + d4);
        }
        const float* kKN = g_kv + (size_t)2 * CBSZ + (size_t)b * 80 * CHID + cb;
        const float* kVN = g_kv + (size_t)3 * CBSZ + (size_t)b * 80 * CHID + cb;
        for (int i = tid; i < CNT * 16; i += 256) {
            const int j = i >> 4, d4 = (i & 15) << 2;
            *(float4*)&S.KNs[hh][j][d4] = *(const float4*)(kKN + (size_t)j * CHID + d4);
            *(float4*)&S.VNs[hh][j][d4] = *(const float4*)(kVN + (size_t)j * CHID + d4);
        }
    }
    const int sidx = idx_alter[b];
    __syncthreads();

    const int warp = tid >> 5, lane = tid & 31;
    const int j0 = lane, j1 = lane + 32, j2 = lane + 64;
    const bool j2ok = (j2 < CLTXT);
    const int j2c = j2ok ? j2 : 0;
    const int d0 = lane << 1;

#pragma unroll
    for (int hh = 0; hh < 2; hh++) {
        const float* k0p = S.Ks[hh][j0];
        const float* k1p = S.Ks[hh][j1];
        const float* k2p = S.Ks[hh][j2c];
        const float* knp = S.KNs[hh][lane & 3];

        float l0[8], l1[8], l2[8], ln[8];
#pragma unroll
        for (int it = 0; it < 8; it++) { l0[it] = l1[it] = l2[it] = ln[it] = 0.f; }

#pragma unroll 4
        for (int d4 = 0; d4 < 64; d4 += 4) {
            const float4 x  = *(const float4*)(k0p + d4);
            const float4 y  = *(const float4*)(k1p + d4);
            const float4 z  = *(const float4*)(k2p + d4);
            const float4 w4 = *(const float4*)(knp + d4);
#pragma unroll
            for (int it = 0; it < 8; it++) {
                const float4 q = *(const float4*)(&S.Qs[hh][warp * 8 + it][d4]);
                l0[it] += q.x * x.x + q.y * x.y + q.z * x.z + q.w * x.w;
                l1[it] += q.x * y.x + q.y * y.y + q.z * y.z + q.w * y.w;
                l2[it] += q.x * z.x + q.y * z.y + q.z * z.z + q.w * z.w;
                ln[it] += q.x * w4.x + q.y * w4.y + q.z * w4.z + q.w * w4.w;
            }
        }

        const float2 vsel = *(const float2*)&S.Vs[hh][sidx][d0];
        const float2 a0v = *(const float2*)&S.VNs[hh][0][d0];
        const float2 a1v = *(const float2*)&S.VNs[hh][1][d0];
        const float2 a2v = *(const float2*)&S.VNs[hh][2][d0];
        const float2 a3v = *(const float2*)&S.VNs[hh][3][d0];
        float vix[8], viy[8];
#pragma unroll
        for (int it = 0; it < 8; it++) {
            const float a0 = l0[it], a1 = l1[it];
            const float a2 = j2ok ? l2[it] : -1e30f;
            float lm = fmaxf(fmaxf(a0, a1), a2);
#pragma unroll
            for (int o = 16; o; o >>= 1) lm = fmaxf(lm, __shfl_xor_sync(0xffffffffu, lm, o));
            const float e0 = __expf(a0 - lm);
            const float e1 = __expf(a1 - lm);
            const float e2 = j2ok ? __expf(a2 - lm) : 0.f;
            float es = e0 + e1 + e2;
#pragma unroll
            for (int o = 16; o; o >>= 1) es += __shfl_xor_sync(0xffffffffu, es, o);
            const float inv = 1.f / es;
            float* wrow = S.Wbuf[warp][it];
            wrow[j0] = e0 * inv;
            wrow[j1] = e1 * inv;
            if (j2ok) wrow[j2] = e2 * inv;

            float lnv = (lane < CNT) ? ln[it] : -1e30f;
            float mn = lnv;
            mn = fmaxf(mn, __shfl_xor_sync(0xffffffffu, mn, 1));
            mn = fmaxf(mn, __shfl_xor_sync(0xffffffffu, mn, 2));
            const float en = __expf(lnv - mn);
            float sn = en;
            sn += __shfl_xor_sync(0xffffffffu, sn, 1);
            sn += __shfl_xor_sync(0xffffffffu, sn, 2);
            const float wnv = en / sn;
            const float wn0 = __shfl_sync(0xffffffffu, wnv, 0);
            const float wn1 = __shfl_sync(0xffffffffu, wnv, 1);
            const float wn2 = __shfl_sync(0xffffffffu, wnv, 2);
            const float wn3 = __shfl_sync(0xffffffffu, wnv, 3);
            vix[it] = wn0 * a0v.x + wn1 * a1v.x + wn2 * a2v.x + wn3 * a3v.x;
            viy[it] = wn0 * a0v.y + wn1 * a1v.y + wn2 * a2v.y + wn3 * a3v.y;
        }
        __syncwarp();

        float bx[8], by[8];
#pragma unroll
        for (int it = 0; it < 8; it++) { bx[it] = 0.f; by[it] = 0.f; }
#pragma unroll 7
        for (int j = 0; j < CLTXT; j++) {
            const float2 vv = *(const float2*)&S.Vs[hh][j][d0];
#pragma unroll
            for (int it = 0; it < 8; it++) {
                const float wj = S.Wbuf[warp][it][j];
                bx[it] += wj * vv.x;
                by[it] += wj * vv.y;
            }
        }

#pragma unroll
        for (int it = 0; it < 8; it++) {
            const float wsel = S.Wbuf[warp][it][sidx];
            const float ox = bx[it] + wsel * (vix[it] - vsel.x);
            const float oy = by[it] + wsel * (viy[it] - vsel.y);
            const int t = warp * 8 + it;
            const size_t off = ((size_t)b * CHW + t0 + t) * CHID + (h0 + hh) * 64 + d0;
            *(__half2*)(g_attn + off) = __floats2half2_rn(ox, oy);
        }
        __syncwarp();
    }
}

// ---------------- launch ----------------
extern "C" void kernel_launch(void* const* d_in, const int* in_sizes, int n_in,
                              void* d_out, int out_size)
{
    (void)in_sizes; (void)n_in; (void)out_size;
    const float* hidden = (const float*)d_in[0];
    const float* enc    = (const float*)d_in[1];
    const int*   idx    = (const int*)  d_in[2];
    const float* Wq     = (const float*)d_in[3];
    const float* Wk     = (const float*)d_in[4];
    const float* Wv     = (const float*)d_in[5];
    const float* Wkn    = (const float*)d_in[6];
    const float* Wvn    = (const float*)d_in[7];
    const float* Wout   = (const float*)d_in[8];
    const float* bout   = (const float*)d_in[9];
    float* out = (float*)d_out;

    __half *hidp, *wqp, *wop, *atp;
    float* qp;
    cudaGetSymbolAddress((void**)&hidp, g_hid);
    cudaGetSymbolAddress((void**)&wqp,  g_wq);
    cudaGetSymbolAddress((void**)&wop,  g_wo);
    cudaGetSymbolAddress((void**)&atp,  g_attn);
    cudaGetSymbolAddress((void**)&qp,   g_q);

    cudaFuncSetAttribute(gemm_f16, cudaFuncAttributeMaxDynamicSharedMemorySize, GEMM_SMEM);
    cudaFuncSetAttribute(qattn_lite, cudaFuncAttributeMaxDynamicSharedMemorySize, (int)sizeof(SmA));

    // fp16 conversions
    cvtf<<<512, 512>>>(hidden, hidp, GM * GK);
    cvtf<<<128, 512>>>(Wq,   wqp, GK * GN);
    cvtf<<<128, 512>>>(Wout, wop, GK * GN);

    // K/V/KN/VN projections + reduce
    proj_splitk<<<dim3(4, CNH, 4 * NSPLIT), 256>>>(enc, Wk, Wv, Wkn, Wvn);
    reduce_proj<<<(4 * CBSZ / 4 + 511) / 512, 512>>>();

    // Q = hidden @ Wq
    gemm_f16<<<dim3(GM / 128, GN / 128), 512, GEMM_SMEM>>>(hidp, wqp, nullptr, qp);

    // attention
    qattn_lite<<<dim3(CB * (CHW / 64), CNH / 2), 256, sizeof(SmA)>>>(idx);

    // out = attn @ Wout + bias
    gemm_f16<<<dim3(GM / 128, GN / 128), 512, GEMM_SMEM>>>(atp, wop, bout, out);
}

// round 9
// speedup vs baseline: 1.6881x; 1.6881x over previous
#include <cuda_runtime.h>
#include <cuda_fp16.h>
#include <cstdint>

#define CB    2
#define CHW   4096
#define CHID  1280
#define CCAD  2048
#define CLTXT 77
#define CNT   4
#define CNH   20
#define CENCL (CLTXT + CNT)

#define GM 8192
#define GK 1280
#define GN 1280
#define CBSZ (CB * 80 * CHID)

// ---------------- scratch (device globals) ----------------
__device__ float g_q[(size_t)GM * GK];
__device__ float g_kv[(size_t)4 * CBSZ];        // [type][b][row<80][1280] fp32
__device__ __half g_hid[(size_t)GM * GK];
__device__ __half g_wq[(size_t)GK * GN];
__device__ __half g_wo[(size_t)GK * GN];
__device__ __half g_attn[(size_t)GM * GK];
__device__ __half g_enc[(size_t)CB * CENCL * CCAD];
__device__ __half g_wk [(size_t)CCAD * CHID];
__device__ __half g_wv [(size_t)CCAD * CHID];
__device__ __half g_wkn[(size_t)CCAD * CHID];
__device__ __half g_wvn[(size_t)CCAD * CHID];

// =====================================================================
// fp32 -> fp16 convert
// =====================================================================
__global__ __launch_bounds__(512) void cvtf(
    const float* __restrict__ x, __half* __restrict__ y, int n)
{
    for (int i = (blockIdx.x * 512 + threadIdx.x) * 4; i < n; i += gridDim.x * 512 * 4) {
        const float4 v = *(const float4*)(x + i);
        *(__half2*)(y + i)     = __floats2half2_rn(v.x, v.y);
        *(__half2*)(y + i + 2) = __floats2half2_rn(v.z, v.w);
    }
}

// =====================================================================
// shared mma helpers
// =====================================================================
#define CP_ASYNC(dst, src) asm volatile("cp.async.cg.shared.global [%0], [%1], 16;" :: "r"(dst), "l"(src))
#define CP_ASYNC_Z(dst, src, ok) asm volatile("cp.async.cg.shared.global [%0], [%1], 16, %2;" :: "r"(dst), "l"(src), "r"((ok) ? 16 : 0))

__device__ __forceinline__ void ldsm4(uint32_t* r, uint32_t a) {
    asm volatile("ldmatrix.sync.aligned.m8n8.x4.shared.b16 {%0,%1,%2,%3}, [%4];"
        : "=r"(r[0]), "=r"(r[1]), "=r"(r[2]), "=r"(r[3]) : "r"(a));
}
__device__ __forceinline__ void ldsm4t(uint32_t* r, uint32_t a) {
    asm volatile("ldmatrix.sync.aligned.m8n8.x4.trans.shared.b16 {%0,%1,%2,%3}, [%4];"
        : "=r"(r[0]), "=r"(r[1]), "=r"(r[2]), "=r"(r[3]) : "r"(a));
}
__device__ __forceinline__ void mma16816(float* c, const uint32_t* a, const uint32_t* b) {
    asm volatile("mma.sync.aligned.m16n8k16.row.col.f32.f16.f16.f32 "
        "{%0,%1,%2,%3}, {%4,%5,%6,%7}, {%8,%9}, {%0,%1,%2,%3};"
        : "+f"(c[0]), "+f"(c[1]), "+f"(c[2]), "+f"(c[3])
        : "r"(a[0]), "r"(a[1]), "r"(a[2]), "r"(a[3]), "r"(b[0]), "r"(b[1]));
}

#define A_PITCH 40
#define B_PITCH 136
#define ABUF (128 * A_PITCH)
#define BBUF (32 * B_PITCH)
#define NSTAGE 4
#define GEMM_SMEM ((NSTAGE * ABUF + NSTAGE * BBUF) * 2)

// =====================================================================
// fp16 mma.sync GEMM: C[GM,GN] = A@B (+bias), fp32 accum
// =====================================================================
__global__ __launch_bounds__(512, 1) void gemm_f16(
    const __half* __restrict__ A, const __half* __restrict__ B,
    const float* __restrict__ bias, float* __restrict__ C)
{
    extern __shared__ __align__(16) char sm[];
    __half* sA = (__half*)sm;
    __half* sB = sA + NSTAGE * ABUF;

    const int tid = threadIdx.x;
    const int m0 = blockIdx.x * 128, n0 = blockIdx.y * 128;
    const int lane = tid & 31, warp = tid >> 5;
    const int wm = warp >> 2, wn = warp & 3;

    const int arow = tid >> 2, ak8 = (tid & 3) << 3;
    const int brow = tid >> 4, bn8 = (tid & 15) << 3;
    const __half* gA = A + (size_t)(m0 + arow) * GK + ak8;
    const __half* gB = B + (size_t)brow * GN + n0 + bn8;
    const uint32_t dA = (uint32_t)__cvta_generic_to_shared(sA) + (uint32_t)(arow * A_PITCH + ak8) * 2;
    const uint32_t dB = (uint32_t)__cvta_generic_to_shared(sB) + (uint32_t)(brow * B_PITCH + bn8) * 2;

#define LOADK(stage, kt) do {                                                   \
        const uint32_t ao_ = (uint32_t)(stage) * (ABUF * 2);                    \
        const uint32_t bo_ = (uint32_t)(stage) * (BBUF * 2);                    \
        const size_t kofs_ = (size_t)(kt) * 32;                                 \
        CP_ASYNC(dA + ao_, gA + kofs_);                                         \
        CP_ASYNC(dB + bo_, gB + kofs_ * GN);                                    \
        asm volatile("cp.async.commit_group;");                                 \
    } while (0)

    LOADK(0, 0);
    LOADK(1, 1);
    LOADK(2, 2);

    float acc[2][4][4] = {};

    const uint32_t aOff = (uint32_t)((wm * 32 + (lane & 15)) * A_PITCH + ((lane >> 4) << 3)) * 2;
    const uint32_t aB0 = (uint32_t)__cvta_generic_to_shared(sA) + aOff;
    const uint32_t bOff = (uint32_t)(((lane & 7) + ((lane >> 3) & 1) * 8) * B_PITCH
                                     + wn * 32 + ((lane >> 4) << 3)) * 2;
    const uint32_t bB0 = (uint32_t)__cvta_generic_to_shared(sB) + bOff;

    const int NKT = GK / 32;   // 40
    for (int kt = 0; kt < NKT; kt++) {
        const int s = kt & (NSTAGE - 1);
        if (kt < NKT - 2)       asm volatile("cp.async.wait_group 2;");
        else if (kt == NKT - 2) asm volatile("cp.async.wait_group 1;");
        else                    asm volatile("cp.async.wait_group 0;");
        __syncthreads();

        const uint32_t ah = aB0 + s * (ABUF * 2);
        const uint32_t bh = bB0 + s * (BBUF * 2);
#pragma unroll
        for (int ks = 0; ks < 2; ks++) {
            const uint32_t ka = ah + ks * 32;
            const uint32_t kb = bh + ks * (16 * B_PITCH * 2);
            uint32_t A0[4], A1[4];
            ldsm4(A0, ka);
            ldsm4(A1, ka + 16 * A_PITCH * 2);
            uint32_t Bf[8];
            ldsm4t(Bf,     kb);
            ldsm4t(Bf + 4, kb + 32);
#pragma unroll
            for (int j = 0; j < 4; j++) {
                mma16816(acc[0][j], A0, &Bf[j * 2]);
                mma16816(acc[1][j], A1, &Bf[j * 2]);
            }
        }
        if (kt + 3 < NKT) {
            LOADK((kt + 3) & (NSTAGE - 1), kt + 3);
        }
    }

#pragma unroll
    for (int fm = 0; fm < 2; fm++) {
        const int r0 = m0 + wm * 32 + fm * 16 + (lane >> 2);
#pragma unroll
        for (int j = 0; j < 4; j++) {
            const int cc = n0 + wn * 32 + j * 8 + ((lane & 3) << 1);
            float b0 = 0.f, b1 = 0.f;
            if (bias) { b0 = bias[cc]; b1 = bias[cc + 1]; }
            *(float2*)(C + (size_t)r0 * GN + cc) =
                make_float2(acc[fm][j][0] + b0, acc[fm][j][1] + b1);
            *(float2*)(C + (size_t)(r0 + 8) * GN + cc) =
                make_float2(acc[fm][j][2] + b0, acc[fm][j][3] + b1);
        }
    }
#undef LOADK
}

// =====================================================================
// fp16 projection GEMM with masked M (K/V/KN/VN -> g_kv fp32)
// grid: (batch 2, N-tile 10, type 4); M-tile 128 covers 77 (txt) / 4 (img)
// =====================================================================
__global__ __launch_bounds__(512, 1) void proj_f16()
{
    extern __shared__ __align__(16) char sm[];
    __half* sA = (__half*)sm;
    __half* sB = sA + NSTAGE * ABUF;

    const int tid = threadIdx.x;
    const int b = blockIdx.x, n0 = blockIdx.y * 128, type = blockIdx.z;
    const int M = (type < 2) ? CLTXT : CNT;
    const __half* Asrc = g_enc + (size_t)b * CENCL * CCAD + ((type >= 2) ? (size_t)CLTXT * CCAD : 0);
    const __half* Bsrc = (type == 0) ? g_wk : (type == 1) ? g_wv : (type == 2) ? g_wkn : g_wvn;
    float* C = g_kv + (size_t)type * CBSZ + (size_t)b * 80 * CHID;

    const int lane = tid & 31, warp = tid >> 5;
    const int wm = warp >> 2, wn = warp & 3;

    const int arow = tid >> 2, ak8 = (tid & 3) << 3;
    const int brow = tid >> 4, bn8 = (tid & 15) << 3;
    const bool aok = arow < M;
    const __half* gA = Asrc + (size_t)arow * CCAD + ak8;
    const __half* gB = Bsrc + (size_t)brow * CHID + n0 + bn8;
    const uint32_t dA = (uint32_t)__cvta_generic_to_shared(sA) + (uint32_t)(arow * A_PITCH + ak8) * 2;
    const uint32_t dB = (uint32_t)__cvta_generic_to_shared(sB) + (uint32_t)(brow * B_PITCH + bn8) * 2;

#define LOADKP(stage, kt) do {                                                  \
        const uint32_t ao_ = (uint32_t)(stage) * (ABUF * 2);                    \
        const uint32_t bo_ = (uint32_t)(stage) * (BBUF * 2);                    \
        const size_t kofs_ = (size_t)(kt) * 32;                                 \
        CP_ASYNC_Z(dA + ao_, gA + kofs_, aok);                                  \
        CP_ASYNC(dB + bo_, gB + kofs_ * CHID);                                  \
        asm volatile("cp.async.commit_group;");                                 \
    } while (0)

    LOADKP(0, 0);
    LOADKP(1, 1);
    LOADKP(2, 2);

    float acc[2][4][4] = {};

    const uint32_t aOff = (uint32_t)((wm * 32 + (lane & 15)) * A_PITCH + ((lane >> 4) << 3)) * 2;
    const uint32_t aB0 = (uint32_t)__cvta_generic_to_shared(sA) + aOff;
    const uint32_t bOff = (uint32_t)(((lane & 7) + ((lane >> 3) & 1) * 8) * B_PITCH
                                     + wn * 32 + ((lane >> 4) << 3)) * 2;
    const uint32_t bB0 = (uint32_t)__cvta_generic_to_shared(sB) + bOff;

    const int NKT = CCAD / 32;   // 64
    for (int kt = 0; kt < NKT; kt++) {
        const int s = kt & (NSTAGE - 1);
        if (kt < NKT - 2)       asm volatile("cp.async.wait_group 2;");
        else if (kt == NKT - 2) asm volatile("cp.async.wait_group 1;");
        else                    asm volatile("cp.async.wait_group 0;");
        __syncthreads();

        const uint32_t ah = aB0 + s * (ABUF * 2);
        const uint32_t bh = bB0 + s * (BBUF * 2);
#pragma unroll
        for (int ks = 0; ks < 2; ks++) {
            const uint32_t ka = ah + ks * 32;
            const uint32_t kb = bh + ks * (16 * B_PITCH * 2);
            uint32_t A0[4], A1[4];
            ldsm4(A0, ka);
            ldsm4(A1, ka + 16 * A_PITCH * 2);
            uint32_t Bf[8];
            ldsm4t(Bf,     kb);
            ldsm4t(Bf + 4, kb + 32);
#pragma unroll
            for (int j = 0; j < 4; j++) {
                mma16816(acc[0][j], A0, &Bf[j * 2]);
                mma16816(acc[1][j], A1, &Bf[j * 2]);
            }
        }
        if (kt + 3 < NKT) {
            LOADKP((kt + 3) & (NSTAGE - 1), kt + 3);
        }
    }

#pragma unroll
    for (int fm = 0; fm < 2; fm++) {
        const int r0 = wm * 32 + fm * 16 + (lane >> 2);
#pragma unroll
        for (int j = 0; j < 4; j++) {
            const int cc = n0 + wn * 32 + j * 8 + ((lane & 3) << 1);
            if (r0 < M)
                *(float2*)(C + (size_t)r0 * CHID + cc) =
                    make_float2(acc[fm][j][0], acc[fm][j][1]);
            if (r0 + 8 < M)
                *(float2*)(C + (size_t)(r0 + 8) * CHID + cc) =
                    make_float2(acc[fm][j][2], acc[fm][j][3]);
        }
    }
#undef LOADKP
}

// =====================================================================
// Attention: token-batched phase 3; output fp16
// =====================================================================
struct SmA {
    float Qs[2][64][68];
    float Ks[2][CLTXT][68];
    float Vs[2][CLTXT][68];
    float KNs[2][CNT][68];
    float VNs[2][CNT][68];
    float Wbuf[8][8][80];
};

__global__ __launch_bounds__(256, 1) void qattn_lite(const int* __restrict__ idx_alter)
{
    extern __shared__ char raw[];
    SmA& S = *reinterpret_cast<SmA*>(raw);
    const int b  = blockIdx.x >> 6;
    const int t0 = (blockIdx.x & 63) << 6;
    const int h0 = blockIdx.y * 2;
    const int tid = threadIdx.x;

    for (int i = tid; i < 64 * 32; i += 256) {
        const int t = i >> 5, c4 = (i & 31) << 2;
        const int hh = c4 >> 6, d = c4 & 63;
        float4 q = *(const float4*)(g_q + ((size_t)b * CHW + t0 + t) * CHID + h0 * 64 + c4);
        q.x *= 0.125f; q.y *= 0.125f; q.z *= 0.125f; q.w *= 0.125f;
        *(float4*)&S.Qs[hh][t][d] = q;
    }

#pragma unroll
    for (int hh = 0; hh < 2; hh++) {
        const size_t cb = (size_t)(h0 + hh) * 64;
        const float* kK = g_kv + (size_t)0 * CBSZ + (size_t)b * 80 * CHID + cb;
        const float* kV = g_kv + (size_t)1 * CBSZ + (size_t)b * 80 * CHID + cb;
        for (int i = tid; i < CLTXT * 16; i += 256) {
            const int j = i >> 4, d4 = (i & 15) << 2;
            *(float4*)&S.Ks[hh][j][d4] = *(const float4*)(kK + (size_t)j * CHID + d4);
            *(float4*)&S.Vs[hh][j][d4] = *(const float4*)(kV + (size_t)j * CHID + d4);
        }
        const float* kKN = g_kv + (size_t)2 * CBSZ + (size_t)b * 80 * CHID + cb;
        const float* kVN = g_kv + (size_t)3 * CBSZ + (size_t)b * 80 * CHID + cb;
        for (int i = tid; i < CNT * 16; i += 256) {
            const int j = i >> 4, d4 = (i & 15) << 2;
            *(float4*)&S.KNs[hh][j][d4] = *(const float4*)(kKN + (size_t)j * CHID + d4);
            *(float4*)&S.VNs[hh][j][d4] = *(const float4*)(kVN + (size_t)j * CHID + d4);
        }
    }
    const int sidx = idx_alter[b];
    __syncthreads();

    const int warp = tid >> 5, lane = tid & 31;
    const int j0 = lane, j1 = lane + 32, j2 = lane + 64;
    const bool j2ok = (j2 < CLTXT);
    const int j2c = j2ok ? j2 : 0;
    const int d0 = lane << 1;

#pragma unroll
    for (int hh = 0; hh < 2; hh++) {
        const float* k0p = S.Ks[hh][j0];
        const float* k1p = S.Ks[hh][j1];
        const float* k2p = S.Ks[hh][j2c];
        const float* knp = S.KNs[hh][lane & 3];

        float l0[8], l1[8], l2[8], ln[8];
#pragma unroll
        for (int it = 0; it < 8; it++) { l0[it] = l1[it] = l2[it] = ln[it] = 0.f; }

#pragma unroll 4
        for (int d4 = 0; d4 < 64; d4 += 4) {
            const float4 x  = *(const float4*)(k0p + d4);
            const float4 y  = *(const float4*)(k1p + d4);
            const float4 z  = *(const float4*)(k2p + d4);
            const float4 w4 = *(const float4*)(knp + d4);
#pragma unroll
            for (int it = 0; it < 8; it++) {
                const float4 q = *(const float4*)(&S.Qs[hh][warp * 8 + it][d4]);
                l0[it] += q.x * x.x + q.y * x.y + q.z * x.z + q.w * x.w;
                l1[it] += q.x * y.x + q.y * y.y + q.z * y.z + q.w * y.w;
                l2[it] += q.x * z.x + q.y * z.y + q.z * z.z + q.w * z.w;
                ln[it] += q.x * w4.x + q.y * w4.y + q.z * w4.z + q.w * w4.w;
            }
        }

        const float2 vsel = *(const float2*)&S.Vs[hh][sidx][d0];
        const float2 a0v = *(const float2*)&S.VNs[hh][0][d0];
        const float2 a1v = *(const float2*)&S.VNs[hh][1][d0];
        const float2 a2v = *(const float2*)&S.VNs[hh][2][d0];
        const float2 a3v = *(const float2*)&S.VNs[hh][3][d0];
        float vix[8], viy[8];
#pragma unroll
        for (int it = 0; it < 8; it++) {
            const float a0 = l0[it], a1 = l1[it];
            const float a2 = j2ok ? l2[it] : -1e30f;
            float lm = fmaxf(fmaxf(a0, a1), a2);
#pragma unroll
            for (int o = 16; o; o >>= 1) lm = fmaxf(lm, __shfl_xor_sync(0xffffffffu, lm, o));
            const float e0 = __expf(a0 - lm);
            const float e1 = __expf(a1 - lm);
            const float e2 = j2ok ? __expf(a2 - lm) : 0.f;
            float es = e0 + e1 + e2;
#pragma unroll
            for (int o = 16; o; o >>= 1) es += __shfl_xor_sync(0xffffffffu, es, o);
            const float inv = 1.f / es;
            float* wrow = S.Wbuf[warp][it];
            wrow[j0] = e0 * inv;
            wrow[j1] = e1 * inv;
            if (j2ok) wrow[j2] = e2 * inv;

            float lnv = (lane < CNT) ? ln[it] : -1e30f;
            float mn = lnv;
            mn = fmaxf(mn, __shfl_xor_sync(0xffffffffu, mn, 1));
            mn = fmaxf(mn, __shfl_xor_sync(0xffffffffu, mn, 2));
            const float en = __expf(lnv - mn);
            float sn = en;
            sn += __shfl_xor_sync(0xffffffffu, sn, 1);
            sn += __shfl_xor_sync(0xffffffffu, sn, 2);
            const float wnv = en / sn;
            const float wn0 = __shfl_sync(0xffffffffu, wnv, 0);
            const float wn1 = __shfl_sync(0xffffffffu, wnv, 1);
            const float wn2 = __shfl_sync(0xffffffffu, wnv, 2);
            const float wn3 = __shfl_sync(0xffffffffu, wnv, 3);
            vix[it] = wn0 * a0v.x + wn1 * a1v.x + wn2 * a2v.x + wn3 * a3v.x;
            viy[it] = wn0 * a0v.y + wn1 * a1v.y + wn2 * a2v.y + wn3 * a3v.y;
        }
        __syncwarp();

        float bx[8], by[8];
#pragma unroll
        for (int it = 0; it < 8; it++) { bx[it] = 0.f; by[it] = 0.f; }
#pragma unroll 7
        for (int j = 0; j < CLTXT; j++) {
            const float2 vv = *(const float2*)&S.Vs[hh][j][d0];
#pragma unroll
            for (int it = 0; it < 8; it++) {
                const float wj = S.Wbuf[warp][it][j];
                bx[it] += wj * vv.x;
                by[it] += wj * vv.y;
            }
        }

#pragma unroll
        for (int it = 0; it < 8; it++) {
            const float wsel = S.Wbuf[warp][it][sidx];
            const float ox = bx[it] + wsel * (vix[it] - vsel.x);
            const float oy = by[it] + wsel * (viy[it] - vsel.y);
            const int t = warp * 8 + it;
            const size_t off = ((size_t)b * CHW + t0 + t) * CHID + (h0 + hh) * 64 + d0;
            *(__half2*)(g_attn + off) = __floats2half2_rn(ox, oy);
        }
        __syncwarp();
    }
}

// ---------------- launch ----------------
extern "C" void kernel_launch(void* const* d_in, const int* in_sizes, int n_in,
                              void* d_out, int out_size)
{
    (void)in_sizes; (void)n_in; (void)out_size;
    const float* hidden = (const float*)d_in[0];
    const float* enc    = (const float*)d_in[1];
    const int*   idx    = (const int*)  d_in[2];
    const float* Wq     = (const float*)d_in[3];
    const float* Wk     = (const float*)d_in[4];
    const float* Wv     = (const float*)d_in[5];
    const float* Wkn    = (const float*)d_in[6];
    const float* Wvn    = (const float*)d_in[7];
    const float* Wout   = (const float*)d_in[8];
    const float* bout   = (const float*)d_in[9];
    float* out = (float*)d_out;

    __half *hidp, *wqp, *wop, *atp, *encp, *wkp, *wvp, *wknp, *wvnp;
    float* qp;
    cudaGetSymbolAddress((void**)&hidp, g_hid);
    cudaGetSymbolAddress((void**)&wqp,  g_wq);
    cudaGetSymbolAddress((void**)&wop,  g_wo);
    cudaGetSymbolAddress((void**)&atp,  g_attn);
    cudaGetSymbolAddress((void**)&encp, g_enc);
    cudaGetSymbolAddress((void**)&wkp,  g_wk);
    cudaGetSymbolAddress((void**)&wvp,  g_wv);
    cudaGetSymbolAddress((void**)&wknp, g_wkn);
    cudaGetSymbolAddress((void**)&wvnp, g_wvn);
    cudaGetSymbolAddress((void**)&qp,   g_q);

    cudaFuncSetAttribute(gemm_f16, cudaFuncAttributeMaxDynamicSharedMemorySize, GEMM_SMEM);
    cudaFuncSetAttribute(proj_f16, cudaFuncAttributeMaxDynamicSharedMemorySize, GEMM_SMEM);
    cudaFuncSetAttribute(qattn_lite, cudaFuncAttributeMaxDynamicSharedMemorySize, (int)sizeof(SmA));

    // fp16 conversions
    cvtf<<<512, 512>>>(hidden, hidp, GM * GK);
    cvtf<<<128, 512>>>(Wq,   wqp, GK * GN);
    cvtf<<<128, 512>>>(Wout, wop, GK * GN);
    cvtf<<<32,  512>>>(enc,  encp, CB * CENCL * CCAD);
    cvtf<<<128, 512>>>(Wk,  wkp,  CCAD * CHID);
    cvtf<<<128, 512>>>(Wv,  wvp,  CCAD * CHID);
    cvtf<<<128, 512>>>(Wkn, wknp, CCAD * CHID);
    cvtf<<<128, 512>>>(Wvn, wvnp, CCAD * CHID);

    // K/V/KN/VN projections on tensor cores -> g_kv fp32
    proj_f16<<<dim3(CB, CHID / 128, 4), 512, GEMM_SMEM>>>();

    // Q = hidden @ Wq
    gemm_f16<<<dim3(GM / 128, GN / 128), 512, GEMM_SMEM>>>(hidp, wqp, nullptr, qp);

    // attention
    qattn_lite<<<dim3(CB * (CHW / 64), CNH / 2), 256, sizeof(SmA)>>>(idx);

    // out = attn @ Wout + bias
    gemm_f16<<<dim3(GM / 128, GN / 128), 512, GEMM_SMEM>>>(atp, wop, bout, out);
}

// round 10
// speedup vs baseline: 1.6906x; 1.0015x over previous
#include <cuda_runtime.h>
#include <cuda_fp16.h>
#include <cstdint>

#define CB    2
#define CHW   4096
#define CHID  1280
#define CCAD  2048
#define CLTXT 77
#define CNT   4
#define CNH   20
#define CENCL (CLTXT + CNT)

#define GM 8192
#define GK 1280
#define GN 1280
#define CBSZ (CB * 80 * CHID)

// ---------------- scratch (device globals) ----------------
__device__ float g_q[(size_t)GM * GK];
__device__ float g_kv[(size_t)4 * CBSZ];
__device__ __half g_hid[(size_t)GM * GK];
__device__ __half g_wq[(size_t)GK * GN];
__device__ __half g_wo[(size_t)GK * GN];
__device__ __half g_attn[(size_t)GM * GK];
__device__ __half g_enc[(size_t)CB * CENCL * CCAD];
__device__ __half g_wk [(size_t)CCAD * CHID];
__device__ __half g_wv [(size_t)CCAD * CHID];
__device__ __half g_wkn[(size_t)CCAD * CHID];
__device__ __half g_wvn[(size_t)CCAD * CHID];

// =====================================================================
// fp32 -> fp16 converts
// =====================================================================
__global__ __launch_bounds__(512) void cvtf(
    const float* __restrict__ x, __half* __restrict__ y, int n)
{
    for (int i = (blockIdx.x * 512 + threadIdx.x) * 4; i < n; i += gridDim.x * 512 * 4) {
        const float4 v = *(const float4*)(x + i);
        *(__half2*)(y + i)     = __floats2half2_rn(v.x, v.y);
        *(__half2*)(y + i + 2) = __floats2half2_rn(v.z, v.w);
    }
}

struct CvtSeg { const float* src; __half* dst; int len; };
struct CvtArgs { CvtSeg s[7]; };

__global__ __launch_bounds__(512) void cvt_multi(CvtArgs a)
{
    const CvtSeg seg = a.s[blockIdx.y];
    const float* __restrict__ x = seg.src;
    __half* __restrict__ y = seg.dst;
    for (int i = (blockIdx.x * 512 + threadIdx.x) * 4; i < seg.len; i += gridDim.x * 512 * 4) {
        const float4 v = *(const float4*)(x + i);
        *(__half2*)(y + i)     = __floats2half2_rn(v.x, v.y);
        *(__half2*)(y + i + 2) = __floats2half2_rn(v.z, v.w);
    }
}

// =====================================================================
// shared mma helpers
// =====================================================================
#define CP_ASYNC(dst, src) asm volatile("cp.async.cg.shared.global [%0], [%1], 16;" :: "r"(dst), "l"(src))
#define CP_ASYNC_Z(dst, src, ok) asm volatile("cp.async.cg.shared.global [%0], [%1], 16, %2;" :: "r"(dst), "l"(src), "r"((ok) ? 16 : 0))

__device__ __forceinline__ void ldsm4(uint32_t* r, uint32_t a) {
    asm volatile("ldmatrix.sync.aligned.m8n8.x4.shared.b16 {%0,%1,%2,%3}, [%4];"
        : "=r"(r[0]), "=r"(r[1]), "=r"(r[2]), "=r"(r[3]) : "r"(a));
}
__device__ __forceinline__ void ldsm4t(uint32_t* r, uint32_t a) {
    asm volatile("ldmatrix.sync.aligned.m8n8.x4.trans.shared.b16 {%0,%1,%2,%3}, [%4];"
        : "=r"(r[0]), "=r"(r[1]), "=r"(r[2]), "=r"(r[3]) : "r"(a));
}
__device__ __forceinline__ void mma16816(float* c, const uint32_t* a, const uint32_t* b) {
    asm volatile("mma.sync.aligned.m16n8k16.row.col.f32.f16.f16.f32 "
        "{%0,%1,%2,%3}, {%4,%5,%6,%7}, {%8,%9}, {%0,%1,%2,%3};"
        : "+f"(c[0]), "+f"(c[1]), "+f"(c[2]), "+f"(c[3])
        : "r"(a[0]), "r"(a[1]), "r"(a[2]), "r"(a[3]), "r"(b[0]), "r"(b[1]));
}

#define A_PITCH 40
#define ABUF (128 * A_PITCH)
#define NSTAGE 4
// proj (128x128 tile) B buffer
#define PB_PITCH 136
#define PBUF (32 * PB_PITCH)
#define PROJ_SMEM ((NSTAGE * ABUF + NSTAGE * PBUF) * 2)
// gemm (128x256 tile) B buffer
#define GB_PITCH 264
#define GBUF (32 * GB_PITCH)
#define GEMM_SMEM ((NSTAGE * ABUF + NSTAGE * GBUF) * 2)

// =====================================================================
// fp16 mma.sync GEMM v4: CTA 128x256, 8 warps (2x4), warp tile 64x64
// =====================================================================
__global__ __launch_bounds__(256, 1) void gemm_f16(
    const __half* __restrict__ A, const __half* __restrict__ B,
    const float* __restrict__ bias, float* __restrict__ C)
{
    extern __shared__ __align__(16) char sm[];
    __half* sA = (__half*)sm;             // [NSTAGE][128][A_PITCH]
    __half* sB = sA + NSTAGE * ABUF;      // [NSTAGE][32][GB_PITCH]

    const int tid = threadIdx.x;
    const int m0 = blockIdx.x * 128, n0 = blockIdx.y * 256;
    const int lane = tid & 31, warp = tid >> 5;
    const int wm = warp & 1, wn = warp >> 1;   // 2 x 4 warps

    // staging: A 2 rows/thread, B 4 rows/thread
    const int arow = tid >> 2, ak8 = (tid & 3) << 3;
    const int brow = tid >> 5, bn8 = (tid & 31) << 3;
    const __half* gA = A + (size_t)(m0 + arow) * GK + ak8;
    const __half* gB = B + (size_t)brow * GN + n0 + bn8;
    const uint32_t dA = (uint32_t)__cvta_generic_to_shared(sA) + (uint32_t)(arow * A_PITCH + ak8) * 2;
    const uint32_t dB = (uint32_t)__cvta_generic_to_shared(sB) + (uint32_t)(brow * GB_PITCH + bn8) * 2;

#define LOADK(stage, kt) do {                                                   \
        const uint32_t ao_ = (uint32_t)(stage) * (ABUF * 2);                    \
        const uint32_t bo_ = (uint32_t)(stage) * (GBUF * 2);                    \
        const size_t ka_ = (size_t)(kt) * 32;                                   \
        CP_ASYNC(dA + ao_, gA + ka_);                                           \
        CP_ASYNC(dA + ao_ + 64 * A_PITCH * 2, gA + (size_t)64 * GK + ka_);      \
        CP_ASYNC(dB + bo_,                     gB + ka_ * GN);                  \
        CP_ASYNC(dB + bo_ +  8 * GB_PITCH * 2, gB + (ka_ +  8) * GN);           \
        CP_ASYNC(dB + bo_ + 16 * GB_PITCH * 2, gB + (ka_ + 16) * GN);           \
        CP_ASYNC(dB + bo_ + 24 * GB_PITCH * 2, gB + (ka_ + 24) * GN);           \
        asm volatile("cp.async.commit_group;");                                 \
    } while (0)

    LOADK(0, 0);
    LOADK(1, 1);
    LOADK(2, 2);

    float acc[4][8][4] = {};

    const uint32_t aOff = (uint32_t)((wm * 64 + (lane & 15)) * A_PITCH + ((lane >> 4) << 3)) * 2;
    const uint32_t aB0 = (uint32_t)__cvta_generic_to_shared(sA) + aOff;
    const uint32_t bOff = (uint32_t)(((lane & 7) + ((lane >> 3) & 1) * 8) * GB_PITCH
                                     + wn * 64 + ((lane >> 4) << 3)) * 2;
    const uint32_t bB0 = (uint32_t)__cvta_generic_to_shared(sB) + bOff;

    const int NKT = GK / 32;   // 40
    for (int kt = 0; kt < NKT; kt++) {
        const int s = kt & (NSTAGE - 1);
        if (kt < NKT - 2)       asm volatile("cp.async.wait_group 2;");
        else if (kt == NKT - 2) asm volatile("cp.async.wait_group 1;");
        else                    asm volatile("cp.async.wait_group 0;");
        __syncthreads();

        const uint32_t ah = aB0 + s * (ABUF * 2);
        const uint32_t bh = bB0 + s * (GBUF * 2);
#pragma unroll
        for (int ks = 0; ks < 2; ks++) {
            const uint32_t ka = ah + ks * 32;                       // +16 halves
            const uint32_t kb = bh + ks * (16 * GB_PITCH * 2);      // +16 k-rows
            uint32_t Af[4][4];
#pragma unroll
            for (int f = 0; f < 4; f++) ldsm4(Af[f], ka + f * (16 * A_PITCH * 2));
            uint32_t Bf[16];
#pragma unroll
            for (int t = 0; t < 4; t++) ldsm4t(Bf + t * 4, kb + t * 32);
#pragma unroll
            for (int f = 0; f < 4; f++)
#pragma unroll
                for (int j = 0; j < 8; j++)
                    mma16816(acc[f][j], Af[f], &Bf[j * 2]);
        }
        if (kt + 3 < NKT) {
            LOADK((kt + 3) & (NSTAGE - 1), kt + 3);
        }
    }

#pragma unroll
    for (int f = 0; f < 4; f++) {
        const int r0 = m0 + wm * 64 + f * 16 + (lane >> 2);
#pragma unroll
        for (int j = 0; j < 8; j++) {
            const int cc = n0 + wn * 64 + j * 8 + ((lane & 3) << 1);
            float b0 = 0.f, b1 = 0.f;
            if (bias) { b0 = bias[cc]; b1 = bias[cc + 1]; }
            *(float2*)(C + (size_t)r0 * GN + cc) =
                make_float2(acc[f][j][0] + b0, acc[f][j][1] + b1);
            *(float2*)(C + (size_t)(r0 + 8) * GN + cc) =
                make_float2(acc[f][j][2] + b0, acc[f][j][3] + b1);
        }
    }
#undef LOADK
}

// =====================================================================
// fp16 projection GEMM, masked M (K/V/KN/VN -> g_kv fp32), CTA 128x128
// =====================================================================
__global__ __launch_bounds__(512, 1) void proj_f16()
{
    extern __shared__ __align__(16) char sm[];
    __half* sA = (__half*)sm;
    __half* sB = sA + NSTAGE * ABUF;

    const int tid = threadIdx.x;
    const int b = blockIdx.x, n0 = blockIdx.y * 128, type = blockIdx.z;
    const int M = (type < 2) ? CLTXT : CNT;
    const __half* Asrc = g_enc + (size_t)b * CENCL * CCAD + ((type >= 2) ? (size_t)CLTXT * CCAD : 0);
    const __half* Bsrc = (type == 0) ? g_wk : (type == 1) ? g_wv : (type == 2) ? g_wkn : g_wvn;
    float* C = g_kv + (size_t)type * CBSZ + (size_t)b * 80 * CHID;

    const int lane = tid & 31, warp = tid >> 5;
    const int wm = warp >> 2, wn = warp & 3;

    const int arow = tid >> 2, ak8 = (tid & 3) << 3;
    const int brow = tid >> 4, bn8 = (tid & 15) << 3;
    const bool aok = arow < M;
    const __half* gA = Asrc + (size_t)arow * CCAD + ak8;
    const __half* gB = Bsrc + (size_t)brow * CHID + n0 + bn8;
    const uint32_t dA = (uint32_t)__cvta_generic_to_shared(sA) + (uint32_t)(arow * A_PITCH + ak8) * 2;
    const uint32_t dB = (uint32_t)__cvta_generic_to_shared(sB) + (uint32_t)(brow * PB_PITCH + bn8) * 2;

#define LOADKP(stage, kt) do {                                                  \
        const uint32_t ao_ = (uint32_t)(stage) * (ABUF * 2);                    \
        const uint32_t bo_ = (uint32_t)(stage) * (PBUF * 2);                    \
        const size_t kofs_ = (size_t)(kt) * 32;                                 \
        CP_ASYNC_Z(dA + ao_, gA + kofs_, aok);                                  \
        CP_ASYNC(dB + bo_, gB + kofs_ * CHID);                                  \
        asm volatile("cp.async.commit_group;");                                 \
    } while (0)

    LOADKP(0, 0);
    LOADKP(1, 1);
    LOADKP(2, 2);

    float acc[2][4][4] = {};

    const uint32_t aOff = (uint32_t)((wm * 32 + (lane & 15)) * A_PITCH + ((lane >> 4) << 3)) * 2;
    const uint32_t aB0 = (uint32_t)__cvta_generic_to_shared(sA) + aOff;
    const uint32_t bOff = (uint32_t)(((lane & 7) + ((lane >> 3) & 1) * 8) * PB_PITCH
                                     + wn * 32 + ((lane >> 4) << 3)) * 2;
    const uint32_t bB0 = (uint32_t)__cvta_generic_to_shared(sB) + bOff;

    const int NKT = CCAD / 32;   // 64
    for (int kt = 0; kt < NKT; kt++) {
        const int s = kt & (NSTAGE - 1);
        if (kt < NKT - 2)       asm volatile("cp.async.wait_group 2;");
        else if (kt == NKT - 2) asm volatile("cp.async.wait_group 1;");
        else                    asm volatile("cp.async.wait_group 0;");
        __syncthreads();

        const uint32_t ah = aB0 + s * (ABUF * 2);
        const uint32_t bh = bB0 + s * (PBUF * 2);
#pragma unroll
        for (int ks = 0; ks < 2; ks++) {
            const uint32_t ka = ah + ks * 32;
            const uint32_t kb = bh + ks * (16 * PB_PITCH * 2);
            uint32_t A0[4], A1[4];
            ldsm4(A0, ka);
            ldsm4(A1, ka + 16 * A_PITCH * 2);
            uint32_t Bf[8];
            ldsm4t(Bf,     kb);
            ldsm4t(Bf + 4, kb + 32);
#pragma unroll
            for (int j = 0; j < 4; j++) {
                mma16816(acc[0][j], A0, &Bf[j * 2]);
                mma16816(acc[1][j], A1, &Bf[j * 2]);
            }
        }
        if (kt + 3 < NKT) {
            LOADKP((kt + 3) & (NSTAGE - 1), kt + 3);
        }
    }

#pragma unroll
    for (int fm = 0; fm < 2; fm++) {
        const int r0 = wm * 32 + fm * 16 + (lane >> 2);
#pragma unroll
        for (int j = 0; j < 4; j++) {
            const int cc = n0 + wn * 32 + j * 8 + ((lane & 3) << 1);
            if (r0 < M)
                *(float2*)(C + (size_t)r0 * CHID + cc) =
                    make_float2(acc[fm][j][0], acc[fm][j][1]);
            if (r0 + 8 < M)
                *(float2*)(C + (size_t)(r0 + 8) * CHID + cc) =
                    make_float2(acc[fm][j][2], acc[fm][j][3]);
        }
    }
#undef LOADKP
}

// =====================================================================
// Attention: token-batched phase 3; output fp16
// =====================================================================
struct SmA {
    float Qs[2][64][68];
    float Ks[2][CLTXT][68];
    float Vs[2][CLTXT][68];
    float KNs[2][CNT][68];
    float VNs[2][CNT][68];
    float Wbuf[8][8][80];
};

__global__ __launch_bounds__(256, 1) void qattn_lite(const int* __restrict__ idx_alter)
{
    extern __shared__ char raw[];
    SmA& S = *reinterpret_cast<SmA*>(raw);
    const int b  = blockIdx.x >> 6;
    const int t0 = (blockIdx.x & 63) << 6;
    const int h0 = blockIdx.y * 2;
    const int tid = threadIdx.x;

    for (int i = tid; i < 64 * 32; i += 256) {
        const int t = i >> 5, c4 = (i & 31) << 2;
        const int hh = c4 >> 6, d = c4 & 63;
        float4 q = *(const float4*)(g_q + ((size_t)b * CHW + t0 + t) * CHID + h0 * 64 + c4);
        q.x *= 0.125f; q.y *= 0.125f; q.z *= 0.125f; q.w *= 0.125f;
        *(float4*)&S.Qs[hh][t][d] = q;
    }

#pragma unroll
    for (int hh = 0; hh < 2; hh++) {
        const size_t cb = (size_t)(h0 + hh) * 64;
        const float* kK = g_kv + (size_t)0 * CBSZ + (size_t)b * 80 * CHID + cb;
        const float* kV = g_kv + (size_t)1 * CBSZ + (size_t)b * 80 * CHID + cb;
        for (int i = tid; i < CLTXT * 16; i += 256) {
            const int j = i >> 4, d4 = (i & 15) << 2;
            *(float4*)&S.Ks[hh][j][d4] = *(const float4*)(kK + (size_t)j * CHID + d4);
            *(float4*)&S.Vs[hh][j][d4] = *(const float4*)(kV + (size_t)j * CHID + d4);
        }
        const float* kKN = g_kv + (size_t)2 * CBSZ + (size_t)b * 80 * CHID + cb;
        const float* kVN = g_kv + (size_t)3 * CBSZ + (size_t)b * 80 * CHID + cb;
        for (int i = tid; i < CNT * 16; i += 256) {
            const int j = i >> 4, d4 = (i & 15) << 2;
            *(float4*)&S.KNs[hh][j][d4] = *(const float4*)(kKN + (size_t)j * CHID + d4);
            *(float4*)&S.VNs[hh][j][d4] = *(const float4*)(kVN + (size_t)j * CHID + d4);
        }
    }
    const int sidx = idx_alter[b];
    __syncthreads();

    const int warp = tid >> 5, lane = tid & 31;
    const int j0 = lane, j1 = lane + 32, j2 = lane + 64;
    const bool j2ok = (j2 < CLTXT);
    const int j2c = j2ok ? j2 : 0;
    const int d0 = lane << 1;

#pragma unroll
    for (int hh = 0; hh < 2; hh++) {
        const float* k0p = S.Ks[hh][j0];
        const float* k1p = S.Ks[hh][j1];
        const float* k2p = S.Ks[hh][j2c];
        const float* knp = S.KNs[hh][lane & 3];

        float l0[8], l1[8], l2[8], ln[8];
#pragma unroll
        for (int it = 0; it < 8; it++) { l0[it] = l1[it] = l2[it] = ln[it] = 0.f; }

#pragma unroll 4
        for (int d4 = 0; d4 < 64; d4 += 4) {
            const float4 x  = *(const float4*)(k0p + d4);
            const float4 y  = *(const float4*)(k1p + d4);
            const float4 z  = *(const float4*)(k2p + d4);
            const float4 w4 = *(const float4*)(knp + d4);
#pragma unroll
            for (int it = 0; it < 8; it++) {
                const float4 q = *(const float4*)(&S.Qs[hh][warp * 8 + it][d4]);
                l0[it] += q.x * x.x + q.y * x.y + q.z * x.z + q.w * x.w;
                l1[it] += q.x * y.x + q.y * y.y + q.z * y.z + q.w * y.w;
                l2[it] += q.x * z.x + q.y * z.y + q.z * z.z + q.w * z.w;
                ln[it] += q.x * w4.x + q.y * w4.y + q.z * w4.z + q.w * w4.w;
            }
        }

        const float2 vsel = *(const float2*)&S.Vs[hh][sidx][d0];
        const float2 a0v = *(const float2*)&S.VNs[hh][0][d0];
        const float2 a1v = *(const float2*)&S.VNs[hh][1][d0];
        const float2 a2v = *(const float2*)&S.VNs[hh][2][d0];
        const float2 a3v = *(const float2*)&S.VNs[hh][3][d0];
        float vix[8], viy[8];
#pragma unroll
        for (int it = 0; it < 8; it++) {
            const float a0 = l0[it], a1 = l1[it];
            const float a2 = j2ok ? l2[it] : -1e30f;
            float lm = fmaxf(fmaxf(a0, a1), a2);
#pragma unroll
            for (int o = 16; o; o >>= 1) lm = fmaxf(lm, __shfl_xor_sync(0xffffffffu, lm, o));
            const float e0 = __expf(a0 - lm);
            const float e1 = __expf(a1 - lm);
            const float e2 = j2ok ? __expf(a2 - lm) : 0.f;
            float es = e0 + e1 + e2;
#pragma unroll
            for (int o = 16; o; o >>= 1) es += __shfl_xor_sync(0xffffffffu, es, o);
            const float inv = 1.f / es;
            float* wrow = S.Wbuf[warp][it];
            wrow[j0] = e0 * inv;
            wrow[j1] = e1 * inv;
            if (j2ok) wrow[j2] = e2 * inv;

            float lnv = (lane < CNT) ? ln[it] : -1e30f;
            float mn = lnv;
            mn = fmaxf(mn, __shfl_xor_sync(0xffffffffu, mn, 1));
            mn = fmaxf(mn, __shfl_xor_sync(0xffffffffu, mn, 2));
            const float en = __expf(lnv - mn);
            float sn = en;
            sn += __shfl_xor_sync(0xffffffffu, sn, 1);
            sn += __shfl_xor_sync(0xffffffffu, sn, 2);
            const float wnv = en / sn;
            const float wn0 = __shfl_sync(0xffffffffu, wnv, 0);
            const float wn1 = __shfl_sync(0xffffffffu, wnv, 1);
            const float wn2 = __shfl_sync(0xffffffffu, wnv, 2);
            const float wn3 = __shfl_sync(0xffffffffu, wnv, 3);
            vix[it] = wn0 * a0v.x + wn1 * a1v.x + wn2 * a2v.x + wn3 * a3v.x;
            viy[it] = wn0 * a0v.y + wn1 * a1v.y + wn2 * a2v.y + wn3 * a3v.y;
        }
        __syncwarp();

        float bx[8], by[8];
#pragma unroll
        for (int it = 0; it < 8; it++) { bx[it] = 0.f; by[it] = 0.f; }
#pragma unroll 7
        for (int j = 0; j < CLTXT; j++) {
            const float2 vv = *(const float2*)&S.Vs[hh][j][d0];
#pragma unroll
            for (int it = 0; it < 8; it++) {
                const float wj = S.Wbuf[warp][it][j];
                bx[it] += wj * vv.x;
                by[it] += wj * vv.y;
            }
        }

#pragma unroll
        for (int it = 0; it < 8; it++) {
            const float wsel = S.Wbuf[warp][it][sidx];
            const float ox = bx[it] + wsel * (vix[it] - vsel.x);
            const float oy = by[it] + wsel * (viy[it] - vsel.y);
            const int t = warp * 8 + it;
            const size_t off = ((size_t)b * CHW + t0 + t) * CHID + (h0 + hh) * 64 + d0;
            *(__half2*)(g_attn + off) = __floats2half2_rn(ox, oy);
        }
        __syncwarp();
    }
}

// ---------------- launch ----------------
extern "C" void kernel_launch(void* const* d_in, const int* in_sizes, int n_in,
                              void* d_out, int out_size)
{
    (void)in_sizes; (void)n_in; (void)out_size;
    const float* hidden = (const float*)d_in[0];
    const float* enc    = (const float*)d_in[1];
    const int*   idx    = (const int*)  d_in[2];
    const float* Wq     = (const float*)d_in[3];
    const float* Wk     = (const float*)d_in[4];
    const float* Wv     = (const float*)d_in[5];
    const float* Wkn    = (const float*)d_in[6];
    const float* Wvn    = (const float*)d_in[7];
    const float* Wout   = (const float*)d_in[8];
    const float* bout   = (const float*)d_in[9];
    float* out = (float*)d_out;

    __half *hidp, *wqp, *wop, *atp, *encp, *wkp, *wvp, *wknp, *wvnp;
    float* qp;
    cudaGetSymbolAddress((void**)&hidp, g_hid);
    cudaGetSymbolAddress((void**)&wqp,  g_wq);
    cudaGetSymbolAddress((void**)&wop,  g_wo);
    cudaGetSymbolAddress((void**)&atp,  g_attn);
    cudaGetSymbolAddress((void**)&encp, g_enc);
    cudaGetSymbolAddress((void**)&wkp,  g_wk);
    cudaGetSymbolAddress((void**)&wvp,  g_wv);
    cudaGetSymbolAddress((void**)&wknp, g_wkn);
    cudaGetSymbolAddress((void**)&wvnp, g_wvn);
    cudaGetSymbolAddress((void**)&qp,   g_q);

    cudaFuncSetAttribute(gemm_f16, cudaFuncAttributeMaxDynamicSharedMemorySize, GEMM_SMEM);
    cudaFuncSetAttribute(proj_f16, cudaFuncAttributeMaxDynamicSharedMemorySize, PROJ_SMEM);
    cudaFuncSetAttribute(qattn_lite, cudaFuncAttributeMaxDynamicSharedMemorySize, (int)sizeof(SmA));

    // 1) batched weight/enc conversions (7 segments, one launch)
    CvtArgs ca;
    ca.s[0] = { Wq,   wqp,  GK * GN };
    ca.s[1] = { Wout, wop,  GK * GN };
    ca.s[2] = { Wk,   wkp,  CCAD * CHID };
    ca.s[3] = { Wv,   wvp,  CCAD * CHID };
    ca.s[4] = { Wkn,  wknp, CCAD * CHID };
    ca.s[5] = { Wvn,  wvnp, CCAD * CHID };
    ca.s[6] = { enc,  encp, CB * CENCL * CCAD };
    cvt_multi<<<dim3(80, 7), 512>>>(ca);

    // 2) hidden conversion
    cvtf<<<512, 512>>>(hidden, hidp, GM * GK);

    // 3) K/V/KN/VN projections -> g_kv fp32
    proj_f16<<<dim3(CB, CHID / 128, 4), 512, PROJ_SMEM>>>();

    // 4) Q = hidden @ Wq
    gemm_f16<<<dim3(GM / 128, GN / 256), 256, GEMM_SMEM>>>(hidp, wqp, nullptr, qp);

    // 5) attention
    qattn_lite<<<dim3(CB * (CHW / 64), CNH / 2), 256, sizeof(SmA)>>>(idx);

    // 6) out = attn @ Wout + bias   (launch #6 -> ncu -s 5 captures THIS)
    gemm_f16<<<dim3(GM / 128, GN / 256), 256, GEMM_SMEM>>>(atp, wop, bout, out);
}